// round 17
// baseline (speedup 1.0000x reference)
#include <cuda_runtime.h>
#include <cstdint>
#include <math.h>

#define B_SZ 4
#define T_SZ 2048
#define C_SZ 768
#define H_SZ 16
#define D_SZ 48
#define M_SZ (B_SZ * T_SZ)          // 8192

// Scratch (device globals: allocation-free rule)
__device__ float g_q[B_SZ * H_SZ * T_SZ * D_SZ];   // [bh][t][d]
__device__ float g_k[B_SZ * H_SZ * T_SZ * D_SZ];
__device__ float g_v[B_SZ * H_SZ * T_SZ * D_SZ];
__device__ float g_ctx[B_SZ * T_SZ * C_SZ];        // [b*t][c]

// ===========================================================================
// mma.sync bf16 (baseline PTX -> HMMA SASS on sm_103)
// ===========================================================================
__device__ __forceinline__ void mma_bf16(float* d, const uint32_t* a, const uint32_t* b)
{
    asm volatile(
        "mma.sync.aligned.m16n8k16.row.col.f32.bf16.bf16.f32 "
        "{%0,%1,%2,%3}, {%4,%5,%6,%7}, {%8,%9}, {%0,%1,%2,%3};"
        : "+f"(d[0]), "+f"(d[1]), "+f"(d[2]), "+f"(d[3])
        : "r"(a[0]), "r"(a[1]), "r"(a[2]), "r"(a[3]), "r"(b[0]), "r"(b[1]));
}

__device__ __forceinline__ uint32_t smem_u32(const void* p) {
    uint32_t a;
    asm("{ .reg .u64 t; cvta.to.shared.u64 t, %1; cvt.u32.u64 %0, t; }" : "=r"(a) : "l"(p));
    return a;
}

#define LDSM_X2_T(r0, r1, addr) \
    asm volatile("ldmatrix.sync.aligned.m8n8.x2.trans.shared.b16 {%0,%1}, [%2];" \
                 : "=r"(r0), "=r"(r1) : "r"(addr))

#define LDSM_X2(r0, r1, addr) \
    asm volatile("ldmatrix.sync.aligned.m8n8.x2.shared.b16 {%0,%1}, [%2];" \
                 : "=r"(r0), "=r"(r1) : "r"(addr))

// split fp32 pair -> bf16x2 hi + bf16x2 lo
__device__ __forceinline__ void pack_pair(uint32_t& hi, uint32_t& lo, float x0, float x1)
{
    asm("cvt.rn.bf16x2.f32 %0, %1, %2;" : "=r"(hi) : "f"(x1), "f"(x0));
    float r0 = x0 - __uint_as_float(hi << 16);
    float r1 = x1 - __uint_as_float(hi & 0xFFFF0000u);
    asm("cvt.rn.bf16x2.f32 %0, %1, %2;" : "=r"(lo) : "f"(r1), "f"(r0));
}

__device__ __forceinline__ void convert4(float4 v, uint2& h, uint2& l)
{
    uint32_t h0, h1, l0, l1;
    asm("cvt.rn.bf16x2.f32 %0, %1, %2;" : "=r"(h0) : "f"(v.y), "f"(v.x));
    asm("cvt.rn.bf16x2.f32 %0, %1, %2;" : "=r"(h1) : "f"(v.w), "f"(v.z));
    float r0 = v.x - __uint_as_float(h0 << 16);
    float r1 = v.y - __uint_as_float(h0 & 0xFFFF0000u);
    float r2 = v.z - __uint_as_float(h1 << 16);
    float r3 = v.w - __uint_as_float(h1 & 0xFFFF0000u);
    asm("cvt.rn.bf16x2.f32 %0, %1, %2;" : "=r"(l0) : "f"(r1), "f"(r0));
    asm("cvt.rn.bf16x2.f32 %0, %1, %2;" : "=r"(l1) : "f"(r3), "f"(r2));
    h = make_uint2(h0, h1);
    l = make_uint2(l0, l1);
}

// ===========================================================================
// Split-precision bf16 tensor-core GEMM (R7 single-buffer structure):
//   out[m,n] = sum_k A[m,k] * W[n,k] + bias[n]
// __launch_bounds__(256,2): 128 regs -> 2 CTAs/SM -> 4 warps/SMSP to hide
// HMMA accumulator-chain latency (prev bottleneck: occ=12.4%, issue=20.5%).
// ===========================================================================
#define SKP 40
#define NKB (C_SZ / 32)

template<bool SPLIT>
__global__ __launch_bounds__(256, 2)
void gemm_mma_kernel(const float* __restrict__ A,
                     const float* __restrict__ W0, const float* __restrict__ W1, const float* __restrict__ W2,
                     const float* __restrict__ b0, const float* __restrict__ b1, const float* __restrict__ b2,
                     float* o0, float* o1, float* o2)
{
    const float* W; const float* bias; float* O;
    if (blockIdx.z == 0)      { W = W0; bias = b0; O = o0; }
    else if (blockIdx.z == 1) { W = W1; bias = b1; O = o1; }
    else                      { W = W2; bias = b2; O = o2; }

    __shared__ __align__(16) uint16_t sm[4][128 * SKP];

    const int tid  = threadIdx.x;
    const int wid  = tid >> 5;
    const int lane = tid & 31;
    const int warp_m = wid & 1;
    const int warp_n = wid >> 1;
    const int m0 = blockIdx.y * 128;
    const int n0 = blockIdx.x * 128;

    const int row = tid >> 1;
    const int hf  = tid & 1;
    const float* Asrc = A + (size_t)(m0 + row) * C_SZ + hf * 16;
    const float* Bsrc = W + (size_t)(n0 + row) * C_SZ + hf * 16;

    float4 pa[4], pb[4];

    auto fetch = [&](int kb) {
        #pragma unroll
        for (int q = 0; q < 4; ++q) {
            pa[q] = *(const float4*)(Asrc + kb * 32 + q * 4);
            pb[q] = *(const float4*)(Bsrc + kb * 32 + q * 4);
        }
    };

    auto cvst = [&]() {
        #pragma unroll
        for (int q = 0; q < 4; ++q) {
            const uint32_t boff = (uint32_t)(row * 80 + (hf * 16 + q * 4) * 2);
            uint2 h, l;
            convert4(pa[q], h, l);
            *(uint2*)((char*)sm[0] + boff) = h;
            *(uint2*)((char*)sm[1] + boff) = l;
            convert4(pb[q], h, l);
            *(uint2*)((char*)sm[2] + boff) = h;
            *(uint2*)((char*)sm[3] + boff) = l;
        }
    };

    float acc[16][4];
    #pragma unroll
    for (int i = 0; i < 16; ++i)
        #pragma unroll
        for (int j = 0; j < 4; ++j) acc[i][j] = 0.0f;

    const int g  = lane >> 2;
    const int tc = lane & 3;
    const uint32_t a_off = (uint32_t)((warp_m * 64 + g) * 80 + tc * 4);
    const uint32_t b_off = (uint32_t)((warp_n * 32 + g) * 80 + tc * 4);

    fetch(0);
    cvst();
    __syncthreads();

    for (int kb = 0; kb < NKB; ++kb) {
        if (kb + 1 < NKB) fetch(kb + 1);

        #pragma unroll
        for (int ks = 0; ks < 2; ++ks) {
            uint32_t ahi[4][4], alo[4][4], bhi[4][2], blo[4][2];
            #pragma unroll
            for (int mt = 0; mt < 4; ++mt) {
                const uint32_t o = a_off + (uint32_t)(mt * 16 * 80 + ks * 32);
                const char* ph = (const char*)sm[0] + o;
                const char* pl = (const char*)sm[1] + o;
                ahi[mt][0] = *(const uint32_t*)ph;
                ahi[mt][1] = *(const uint32_t*)(ph + 8 * 80);
                ahi[mt][2] = *(const uint32_t*)(ph + 16);
                ahi[mt][3] = *(const uint32_t*)(ph + 8 * 80 + 16);
                alo[mt][0] = *(const uint32_t*)pl;
                alo[mt][1] = *(const uint32_t*)(pl + 8 * 80);
                alo[mt][2] = *(const uint32_t*)(pl + 16);
                alo[mt][3] = *(const uint32_t*)(pl + 8 * 80 + 16);
            }
            #pragma unroll
            for (int nt = 0; nt < 4; ++nt) {
                const uint32_t o = b_off + (uint32_t)(nt * 8 * 80 + ks * 32);
                const char* ph = (const char*)sm[2] + o;
                const char* pl = (const char*)sm[3] + o;
                bhi[nt][0] = *(const uint32_t*)ph;
                bhi[nt][1] = *(const uint32_t*)(ph + 16);
                blo[nt][0] = *(const uint32_t*)pl;
                blo[nt][1] = *(const uint32_t*)(pl + 16);
            }
            #pragma unroll
            for (int mt = 0; mt < 4; ++mt)
                #pragma unroll
                for (int nt = 0; nt < 4; ++nt) {
                    mma_bf16(acc[mt * 4 + nt], ahi[mt], bhi[nt]);
                    mma_bf16(acc[mt * 4 + nt], ahi[mt], blo[nt]);
                    mma_bf16(acc[mt * 4 + nt], alo[mt], bhi[nt]);
                }
        }
        __syncthreads();
        if (kb + 1 < NKB) {
            cvst();
            __syncthreads();
        }
    }

    #pragma unroll
    for (int mt = 0; mt < 4; ++mt) {
        const int rm = m0 + warp_m * 64 + mt * 16 + g;
        #pragma unroll
        for (int nt = 0; nt < 4; ++nt) {
            const int n = n0 + warp_n * 32 + nt * 8 + tc * 2;
            const float* ac = acc[mt * 4 + nt];
            float bv0 = __ldg(bias + n), bv1 = __ldg(bias + n + 1);
            if (SPLIT) {
                #pragma unroll
                for (int e = 0; e < 4; ++e) {
                    int m = rm + (e >> 1) * 8;
                    int nn = n + (e & 1);
                    float v = ac[e] + ((e & 1) ? bv1 : bv0);
                    int b = m >> 11;
                    int t = m & (T_SZ - 1);
                    int h = nn / D_SZ;
                    int d = nn - h * D_SZ;
                    O[(((size_t)(b * H_SZ + h)) * T_SZ + t) * D_SZ + d] = v;
                }
            } else {
                *(float2*)(O + (size_t)rm * C_SZ + n)       = make_float2(ac[0] + bv0, ac[1] + bv1);
                *(float2*)(O + (size_t)(rm + 8) * C_SZ + n) = make_float2(ac[2] + bv0, ac[3] + bv1);
            }
        }
    }
}

// ---------------------------------------------------------------------------
// RoPE, in-place on Q and K ([bh][t][48] layout)
// ---------------------------------------------------------------------------
__global__ __launch_bounds__(256)
void rope_kernel(float* __restrict__ q, float* __restrict__ k)
{
    const int total = B_SZ * H_SZ * T_SZ * (D_SZ / 2);
    int idx = blockIdx.x * blockDim.x + threadIdx.x;
    if (idx >= total) return;
    int j   = idx % (D_SZ / 2);
    int row = idx / (D_SZ / 2);
    int t   = row & (T_SZ - 1);

    float inv = (float)exp(-log(10000.0) * (double)j / 24.0);
    float ang = (float)t * inv;
    float s, c;
    sincosf(ang, &s, &c);

    float* qp = q + (size_t)row * D_SZ;
    float q1 = qp[j], q2 = qp[j + 24];
    qp[j]      = q1 * c - q2 * s;
    qp[j + 24] = q2 * c + q1 * s;

    float* kp = k + (size_t)row * D_SZ;
    float k1 = kp[j], k2 = kp[j + 24];
    kp[j]      = k1 * c - k2 * s;
    kp[j + 24] = k2 * c + k1 * s;
}

// ===========================================================================
// Tensor-core flash attention (split-precision bf16 mma).
// CTA = 128 q rows (8 warps x 16 rows). Outer tile = 128 keys, 2x64 inner.
// __launch_bounds__(256,2): 2 CTAs/SM for latency hiding.
// K B-fragments via ldmatrix.x2 (non-trans): 1 LDSM replaces 4 LDS.32.
// exp on MUFU; P and V both kept in hi/lo split (precision analysis: dropping
// either gives ~6.5e-4 output error -> too close to the 1e-3 threshold).
// ===========================================================================
#define KV_PITCH 112
#define SM_KH 0
#define SM_KL 14336
#define SM_VH 28672
#define SM_VL 43008
#define SM_MADD 57344
#define ATT_SMEM (57344 + 512 + 128)

__global__ __launch_bounds__(256, 2)
void attn_mma_kernel(const float* __restrict__ Q, const float* __restrict__ K,
                     const float* __restrict__ V, const float* __restrict__ mask,
                     float* __restrict__ ctx)
{
    extern __shared__ __align__(16) char sbuf[];
    const uint32_t sb = smem_u32(sbuf);

    const int tid  = threadIdx.x;
    const int wid  = tid >> 5;
    const int lane = tid & 31;
    const int g    = lane >> 2;
    const int tc   = lane & 3;

    const int qblk = (int)gridDim.x - 1 - (int)blockIdx.x;  // big CTAs first
    const int q0 = qblk * 128;
    const int bh = blockIdx.y;
    const int b = bh >> 4;
    const int h = bh & 15;
    const float scale = 0.14433756729740643f;   // 1/sqrt(48)

    // ---- stage Q (fp32) into smem (aliases K/V area), build scaled hi/lo frags
    {
        const float4* qg = (const float4*)(Q + ((size_t)bh * T_SZ + q0) * D_SZ);
        float4* qs4 = (float4*)sbuf;
        #pragma unroll
        for (int u = 0; u < 6; ++u) qs4[tid + u * 256] = qg[tid + u * 256];
    }
    __syncthreads();

    uint32_t qhi[3][4], qlo[3][4];
    {
        const float* qs = (const float*)sbuf;
        const int qr0 = wid * 16 + g;
        #pragma unroll
        for (int ks = 0; ks < 3; ++ks)
            #pragma unroll
            for (int hh = 0; hh < 2; ++hh) {
                int d0 = ks * 16 + hh * 8 + 2 * tc;
                float x0 = qs[qr0 * 48 + d0] * scale;
                float x1 = qs[qr0 * 48 + d0 + 1] * scale;
                float y0 = qs[(qr0 + 8) * 48 + d0] * scale;
                float y1 = qs[(qr0 + 8) * 48 + d0 + 1] * scale;
                pack_pair(qhi[ks][hh * 2],     qlo[ks][hh * 2],     x0, x1);
                pack_pair(qhi[ks][hh * 2 + 1], qlo[ks][hh * 2 + 1], y0, y1);
            }
    }
    __syncthreads();

    float oacc[6][4];
    #pragma unroll
    for (int i = 0; i < 6; ++i)
        #pragma unroll
        for (int j = 0; j < 4; ++j) oacc[i][j] = 0.0f;
    float mrow0 = -1e30f, mrow1 = -1e30f, rs0 = 0.0f, rs1 = 0.0f;

    const int rowg0 = q0 + wid * 16 + g;
    const int rowg1 = rowg0 + 8;
    const int ntiles = qblk + 1;

    // ldmatrix address lanes: rows via lane&7, +16B for lanes 8-15
    const uint32_t krow_base = sb + (uint32_t)((lane & 7) * KV_PITCH + ((lane >> 3) & 1) * 16);

    for (int tile = 0; tile < ntiles; ++tile) {
        const int j0 = tile * 128;
        // ---- load 128 keys of K,V; convert to bf16 hi/lo
        {
            const float4* kg = (const float4*)(K + ((size_t)bh * T_SZ + j0) * D_SZ);
            const float4* vg = (const float4*)(V + ((size_t)bh * T_SZ + j0) * D_SZ);
            #pragma unroll
            for (int u = 0; u < 6; ++u) {
                int idx = tid + u * 256;
                int key = idx / 12;
                int dq  = idx - key * 12;
                uint32_t so = (uint32_t)(key * KV_PITCH + dq * 8);
                uint2 hh, ll;
                convert4(kg[idx], hh, ll);
                *(uint2*)(sbuf + SM_KH + so) = hh;
                *(uint2*)(sbuf + SM_KL + so) = ll;
                convert4(vg[idx], hh, ll);
                *(uint2*)(sbuf + SM_VH + so) = hh;
                *(uint2*)(sbuf + SM_VL + so) = ll;
            }
            if (tid < 128)
                ((float*)(sbuf + SM_MADD))[tid] =
                    (1.0f - mask[b * T_SZ + j0 + tid]) * -10000.0f;
        }
        __syncthreads();

        const bool needmask = (tile == ntiles - 1);

        #pragma unroll 1
        for (int half = 0; half < 2; ++half) {
            const int jh = j0 + half * 64;

            // ---- S = Qs * K^T  (split precision; K frags via ldmatrix.x2)
            float sfr[8][4];
            const uint32_t kh_base = krow_base + SM_KH + (uint32_t)(half * 64 * KV_PITCH);
            #pragma unroll
            for (int nt = 0; nt < 8; ++nt) {
                sfr[nt][0] = sfr[nt][1] = sfr[nt][2] = sfr[nt][3] = 0.0f;
                const uint32_t kh = kh_base + (uint32_t)(nt * 8 * KV_PITCH);
                const uint32_t kl = kh + (uint32_t)(SM_KL - SM_KH);
                #pragma unroll
                for (int ks = 0; ks < 3; ++ks) {
                    uint32_t bh2[2], bl2[2];
                    LDSM_X2(bh2[0], bh2[1], kh + ks * 32);
                    LDSM_X2(bl2[0], bl2[1], kl + ks * 32);
                    mma_bf16(sfr[nt], qhi[ks], bh2);
                    mma_bf16(sfr[nt], qhi[ks], bl2);
                    mma_bf16(sfr[nt], qlo[ks], bh2);
                }
            }

            // ---- masks
            const float* smadd = (const float*)(sbuf + SM_MADD) + half * 64;
            #pragma unroll
            for (int nt = 0; nt < 8; ++nt) {
                float sa0 = smadd[nt * 8 + 2 * tc];
                float sa1 = smadd[nt * 8 + 2 * tc + 1];
                sfr[nt][0] += sa0; sfr[nt][1] += sa1;
                sfr[nt][2] += sa0; sfr[nt][3] += sa1;
                if (needmask) {
                    int c0i = jh + nt * 8 + 2 * tc;
                    int c1i = c0i + 1;
                    if (c0i > rowg0) sfr[nt][0] = -1e30f;
                    if (c1i > rowg0) sfr[nt][1] = -1e30f;
                    if (c0i > rowg1) sfr[nt][2] = -1e30f;
                    if (c1i > rowg1) sfr[nt][3] = -1e30f;
                }
            }

            // ---- online softmax (exp on MUFU)
            float cm0 = -1e30f, cm1 = -1e30f;
            #pragma unroll
            for (int nt = 0; nt < 8; ++nt) {
                cm0 = fmaxf(cm0, fmaxf(sfr[nt][0], sfr[nt][1]));
                cm1 = fmaxf(cm1, fmaxf(sfr[nt][2], sfr[nt][3]));
            }
            cm0 = fmaxf(cm0, __shfl_xor_sync(0xffffffffu, cm0, 1));
            cm0 = fmaxf(cm0, __shfl_xor_sync(0xffffffffu, cm0, 2));
            cm1 = fmaxf(cm1, __shfl_xor_sync(0xffffffffu, cm1, 1));
            cm1 = fmaxf(cm1, __shfl_xor_sync(0xffffffffu, cm1, 2));
            float mn0 = fmaxf(mrow0, cm0), mn1 = fmaxf(mrow1, cm1);
            float al0 = __expf(mrow0 - mn0), al1 = __expf(mrow1 - mn1);
            mrow0 = mn0; mrow1 = mn1;
            rs0 *= al0; rs1 *= al1;
            #pragma unroll
            for (int ntd = 0; ntd < 6; ++ntd) {
                oacc[ntd][0] *= al0; oacc[ntd][1] *= al0;
                oacc[ntd][2] *= al1; oacc[ntd][3] *= al1;
            }
            #pragma unroll
            for (int nt = 0; nt < 8; ++nt) {
                float p0 = __expf(sfr[nt][0] - mn0);
                float p1 = __expf(sfr[nt][1] - mn0);
                float p2 = __expf(sfr[nt][2] - mn1);
                float p3 = __expf(sfr[nt][3] - mn1);
                rs0 += p0 + p1; rs1 += p2 + p3;
                sfr[nt][0] = p0; sfr[nt][1] = p1;
                sfr[nt][2] = p2; sfr[nt][3] = p3;
            }

            // ---- O += P * V  (P frags from S frags; V via ldmatrix.trans)
            const uint32_t vrow_h = sb + SM_VH +
                (uint32_t)((half * 64 + (lane & 15)) * KV_PITCH);
            const uint32_t vrow_l = vrow_h + (uint32_t)(SM_VL - SM_VH);
            #pragma unroll
            for (int ks = 0; ks < 4; ++ks) {
                uint32_t aph[4], apl[4];
                pack_pair(aph[0], apl[0], sfr[2 * ks][0],     sfr[2 * ks][1]);
                pack_pair(aph[1], apl[1], sfr[2 * ks][2],     sfr[2 * ks][3]);
                pack_pair(aph[2], apl[2], sfr[2 * ks + 1][0], sfr[2 * ks + 1][1]);
                pack_pair(aph[3], apl[3], sfr[2 * ks + 1][2], sfr[2 * ks + 1][3]);
                const uint32_t rh = vrow_h + (uint32_t)(ks * 16 * KV_PITCH);
                const uint32_t rl = vrow_l + (uint32_t)(ks * 16 * KV_PITCH);
                #pragma unroll
                for (int ntd = 0; ntd < 6; ++ntd) {
                    uint32_t bvh[2], bvl[2];
                    LDSM_X2_T(bvh[0], bvh[1], rh + ntd * 16);
                    LDSM_X2_T(bvl[0], bvl[1], rl + ntd * 16);
                    mma_bf16(oacc[ntd], aph, bvh);
                    mma_bf16(oacc[ntd], aph, bvl);
                    mma_bf16(oacc[ntd], apl, bvh);
                }
            }
        }
        __syncthreads();
    }

    // ---- epilogue
    rs0 += __shfl_xor_sync(0xffffffffu, rs0, 1);
    rs0 += __shfl_xor_sync(0xffffffffu, rs0, 2);
    rs1 += __shfl_xor_sync(0xffffffffu, rs1, 1);
    rs1 += __shfl_xor_sync(0xffffffffu, rs1, 2);
    const float i0 = 1.0f / rs0, i1 = 1.0f / rs1;

    float* base0 = ctx + ((size_t)b * T_SZ + rowg0) * C_SZ + h * D_SZ;
    float* base1 = ctx + ((size_t)b * T_SZ + rowg1) * C_SZ + h * D_SZ;
    #pragma unroll
    for (int ntd = 0; ntd < 6; ++ntd) {
        *(float2*)(base0 + ntd * 8 + 2 * tc) = make_float2(oacc[ntd][0] * i0, oacc[ntd][1] * i0);
        *(float2*)(base1 + ntd * 8 + 2 * tc) = make_float2(oacc[ntd][2] * i1, oacc[ntd][3] * i1);
    }
}

// ---------------------------------------------------------------------------
extern "C" void kernel_launch(void* const* d_in, const int* in_sizes, int n_in,
                              void* d_out, int out_size)
{
    const float* hs    = (const float*)d_in[0];
    const float* amask = (const float*)d_in[1];
    const float* Wq = (const float*)d_in[2]; const float* bq = (const float*)d_in[3];
    const float* Wk = (const float*)d_in[4]; const float* bk = (const float*)d_in[5];
    const float* Wv = (const float*)d_in[6]; const float* bv = (const float*)d_in[7];
    const float* Wo = (const float*)d_in[8]; const float* bo = (const float*)d_in[9];
    float* out = (float*)d_out;

    float *q_ptr, *k_ptr, *v_ptr, *ctx_ptr;
    cudaGetSymbolAddress((void**)&q_ptr,   g_q);
    cudaGetSymbolAddress((void**)&k_ptr,   g_k);
    cudaGetSymbolAddress((void**)&v_ptr,   g_v);
    cudaGetSymbolAddress((void**)&ctx_ptr, g_ctx);

    cudaFuncSetAttribute(attn_mma_kernel, cudaFuncAttributeMaxDynamicSharedMemorySize, ATT_SMEM);

    // 1. Fused QKV projections -> head-split layouts (tensor cores)
    dim3 g1(C_SZ / 128, M_SZ / 128, 3);
    gemm_mma_kernel<true><<<g1, 256>>>(hs, Wq, Wk, Wv, bq, bk, bv,
                                       q_ptr, k_ptr, v_ptr);

    // 2. RoPE in place on Q, K
    const int rope_total = B_SZ * H_SZ * T_SZ * (D_SZ / 2);
    rope_kernel<<<(rope_total + 255) / 256, 256>>>(q_ptr, k_ptr);

    // 3. Causal flash attention on tensor cores -> ctx [M, C]
    attn_mma_kernel<<<dim3(T_SZ / 128, B_SZ * H_SZ), 256, ATT_SMEM>>>(
        q_ptr, k_ptr, v_ptr, amask, ctx_ptr);

    // 4. Output projection -> d_out (tensor cores)
    dim3 g4(C_SZ / 128, M_SZ / 128, 1);
    gemm_mma_kernel<false><<<g4, 256>>>(ctx_ptr, Wo, Wo, Wo, bo, bo, bo,
                                        out, out, out);
}